// round 2
// baseline (speedup 1.0000x reference)
#include <cuda_runtime.h>
#include <cstdint>

// ---------------------------------------------------------------------------
// Problem constants
// ---------------------------------------------------------------------------
constexpr int NTOK = 8192;   // tokens
constexpr int DIM  = 1024;   // model dim
constexpr int HID  = 4096;   // expert hidden
constexpr int NE   = 8;      // experts
constexpr int NC   = 8;      // classes
constexpr int NCAP = 8192;   // per-expert capacity (worst case all tokens)

// GEMM tile config
constexpr int BM = 128, BN = 128, BK = 32;
constexpr int SA_STRIDE = BM + 8;   // stride % 32 == 8 -> conflict-free frag reads
constexpr int SB_STRIDE = BN + 8;
constexpr int SMEM_BYTES = (2 * BK * SA_STRIDE + 2 * BK * SB_STRIDE) * 4; // 69632

// ---------------------------------------------------------------------------
// Device scratch (static: no allocation allowed in kernel_launch)
// ---------------------------------------------------------------------------
__device__ float g_pre[(size_t)NTOK * DIM];          // x@Wp + bp
__device__ float g_hidden[(size_t)NTOK * DIM];       // LN(pre)
__device__ float g_h1[(size_t)2 * NTOK * HID];       // ragged gelu(h@W1+b1), 256MB
__device__ float g_contrib[(size_t)2 * NTOK * DIM];  // per (token,slot) FFN output
__device__ float g_final[(size_t)NTOK * DIM];        // after double LN
__device__ int   g_cnt[NE];
__device__ int   g_off[NE];
__device__ int   g_list[NE * NCAP];                  // token index per list entry
__device__ int   g_tokslot[NE * NCAP];               // token*2 + slot
__device__ float g_gatev[NE * NCAP];                 // renormalized gate

// ---------------------------------------------------------------------------
// Helpers
// ---------------------------------------------------------------------------
__device__ __forceinline__ uint32_t f2tf32(float x) {
    uint32_t y;
    asm("cvt.rna.tf32.f32 %0, %1;" : "=r"(y) : "f"(x));
    return y;
}

__device__ __forceinline__ void mma_tf32(float* d, const uint32_t* a, const uint32_t* b) {
    asm volatile(
        "mma.sync.aligned.m16n8k8.row.col.f32.tf32.tf32.f32 "
        "{%0,%1,%2,%3}, {%4,%5,%6,%7}, {%8,%9}, {%0,%1,%2,%3};\n"
        : "+f"(d[0]), "+f"(d[1]), "+f"(d[2]), "+f"(d[3])
        : "r"(a[0]), "r"(a[1]), "r"(a[2]), "r"(a[3]), "r"(b[0]), "r"(b[1]));
}

__device__ __forceinline__ float gelu_t(float x) {
    // jax.nn.gelu default: tanh approximation
    return 0.5f * x * (1.f + tanhf(0.7978845608028654f * (x + 0.044715f * x * x * x)));
}

// Block-wide mean/rstd over a 1024-wide row held as one float4/thread (256 thr)
__device__ __forceinline__ void row_stats1024(float s, float q, float& mu, float& rstd) {
    __shared__ float shs[8], shq[8];
    #pragma unroll
    for (int o = 16; o; o >>= 1) {
        s += __shfl_xor_sync(0xffffffffu, s, o);
        q += __shfl_xor_sync(0xffffffffu, q, o);
    }
    int w = threadIdx.x >> 5;
    __syncthreads();                       // protect prior use of shs/shq
    if ((threadIdx.x & 31) == 0) { shs[w] = s; shq[w] = q; }
    __syncthreads();
    float ts = 0.f, tq = 0.f;
    #pragma unroll
    for (int k = 0; k < 8; k++) { ts += shs[k]; tq += shq[k]; }
    mu = ts * (1.f / DIM);
    float var = tq * (1.f / DIM) - mu * mu;
    rstd = rsqrtf(var + 1e-5f);
}

// ---------------------------------------------------------------------------
// Core tiled GEMM, fp32-accurate via 3xTF32 error compensation:
//   a*b ~= a_lo*b_hi + a_hi*b_lo + a_hi*b_hi   (lo*lo dropped, ~2e-7 rel)
//  MODE 0: g_pre[r]        = x @ Wp + bp                (M=NTOK fixed)
//  MODE 1: g_h1[off+r]     = gelu(gather(hidden) @ W1[e] + b1[e])   (M=cnt[e])
//  MODE 2: g_contrib[dst]  = gate * (g_h1 @ W2[e] + b2[e])          (M=cnt[e])
// ---------------------------------------------------------------------------
template <int MODE>
__global__ void __launch_bounds__(256)
gemm_tpl(const float* __restrict__ A, const float* __restrict__ Bmat,
         const float* __restrict__ bias, int K, int Nw, int ldA) {
    extern __shared__ float smem[];
    float* sA = smem;
    float* sB = smem + 2 * BK * SA_STRIDE;

    const int e = blockIdx.z;
    int M;
    const float* Ap;
    const int* ridx = nullptr;
    int obase = 0;
    if (MODE == 0) {
        M = NTOK; Ap = A;
    } else if (MODE == 1) {
        M = g_cnt[e]; Ap = g_hidden; ridx = g_list + e * NCAP; obase = g_off[e];
    } else {
        M = g_cnt[e]; Ap = g_h1 + (size_t)g_off[e] * HID;
    }
    if ((int)blockIdx.y * BM >= M) return;

    const float* Bp    = Bmat + (size_t)e * K * Nw;
    const float* biasP = bias + (size_t)e * Nw;

    const int tid  = threadIdx.x;
    const int lane = tid & 31, warp = tid >> 5;
    const int wm = warp & 1, wn = warp >> 1;     // 2 warps M x 4 warps N
    const int g = lane >> 2, c = lane & 3;
    const int mBase = blockIdx.y * BM;
    const int nBase = blockIdx.x * BN;

    float acc[4][4][4];
    #pragma unroll
    for (int i = 0; i < 4; i++)
        #pragma unroll
        for (int j = 0; j < 4; j++)
            #pragma unroll
            for (int k = 0; k < 4; k++) acc[i][j][k] = 0.f;

    float4 ar[4], br[4];

    auto LOADT = [&](int kt) {
        const int ka = kt * BK + warp * 4;     // A: warp picks 4 k-cols
        #pragma unroll
        for (int p = 0; p < 4; p++) {
            int mg = mBase + lane + 32 * p;    // lane picks row
            float4 v = make_float4(0.f, 0.f, 0.f, 0.f);
            if (mg < M) {
                int row = (MODE == 1) ? ridx[mg] : mg;
                v = *reinterpret_cast<const float4*>(Ap + (size_t)row * ldA + ka);
            }
            ar[p] = v;
        }
        const int kb = kt * BK + warp;         // B: warp picks k-row
        #pragma unroll
        for (int p = 0; p < 4; p++)
            br[p] = *reinterpret_cast<const float4*>(
                Bp + (size_t)(kb + 8 * p) * Nw + nBase + lane * 4);
    };

    auto STORET = [&](int buf) {
        float* a0 = sA + buf * BK * SA_STRIDE;
        #pragma unroll
        for (int p = 0; p < 4; p++) {
            int ml = lane + 32 * p;
            a0[(warp * 4 + 0) * SA_STRIDE + ml] = ar[p].x;
            a0[(warp * 4 + 1) * SA_STRIDE + ml] = ar[p].y;
            a0[(warp * 4 + 2) * SA_STRIDE + ml] = ar[p].z;
            a0[(warp * 4 + 3) * SA_STRIDE + ml] = ar[p].w;
        }
        float* b0 = sB + buf * BK * SB_STRIDE;
        #pragma unroll
        for (int p = 0; p < 4; p++)
            *reinterpret_cast<float4*>(b0 + (warp + 8 * p) * SB_STRIDE + lane * 4) = br[p];
    };

    const int nkt = K / BK;
    LOADT(0);
    STORET(0);
    __syncthreads();

    for (int kt = 0; kt < nkt; kt++) {
        if (kt + 1 < nkt) LOADT(kt + 1);     // overlap gmem with compute
        const int cur = kt & 1;
        const float* a0 = sA + cur * BK * SA_STRIDE;
        const float* b0 = sB + cur * BK * SB_STRIDE;
        #pragma unroll
        for (int ks = 0; ks < 4; ks++) {
            const int k0 = ks * 8 + c;
            // fragment loads (fp32) + one-time hi/lo tf32 split
            uint32_t ah[4][4], al[4][4], bh[4][2], bl[4][2];
            #pragma unroll
            for (int i = 0; i < 4; i++) {
                int m = wm * 64 + i * 16 + g;
                float v0 = a0[k0 * SA_STRIDE + m];
                float v1 = a0[k0 * SA_STRIDE + m + 8];
                float v2 = a0[(k0 + 4) * SA_STRIDE + m];
                float v3 = a0[(k0 + 4) * SA_STRIDE + m + 8];
                ah[i][0] = f2tf32(v0); al[i][0] = f2tf32(v0 - __uint_as_float(ah[i][0]));
                ah[i][1] = f2tf32(v1); al[i][1] = f2tf32(v1 - __uint_as_float(ah[i][1]));
                ah[i][2] = f2tf32(v2); al[i][2] = f2tf32(v2 - __uint_as_float(ah[i][2]));
                ah[i][3] = f2tf32(v3); al[i][3] = f2tf32(v3 - __uint_as_float(ah[i][3]));
            }
            #pragma unroll
            for (int j = 0; j < 4; j++) {
                int n = wn * 32 + j * 8 + g;
                float w0 = b0[k0 * SB_STRIDE + n];
                float w1 = b0[(k0 + 4) * SB_STRIDE + n];
                bh[j][0] = f2tf32(w0); bl[j][0] = f2tf32(w0 - __uint_as_float(bh[j][0]));
                bh[j][1] = f2tf32(w1); bl[j][1] = f2tf32(w1 - __uint_as_float(bh[j][1]));
            }
            // 3-term compensated accumulation
            #pragma unroll
            for (int i = 0; i < 4; i++)
                #pragma unroll
                for (int j = 0; j < 4; j++)
                    mma_tf32(acc[i][j], al[i], bh[j]);
            #pragma unroll
            for (int i = 0; i < 4; i++)
                #pragma unroll
                for (int j = 0; j < 4; j++)
                    mma_tf32(acc[i][j], ah[i], bl[j]);
            #pragma unroll
            for (int i = 0; i < 4; i++)
                #pragma unroll
                for (int j = 0; j < 4; j++)
                    mma_tf32(acc[i][j], ah[i], bh[j]);
        }
        __syncthreads();
        if (kt + 1 < nkt) { STORET((kt + 1) & 1); __syncthreads(); }
    }

    // Epilogue
    #pragma unroll
    for (int i = 0; i < 4; i++) {
        int r0 = mBase + wm * 64 + i * 16 + g;
        int r1 = r0 + 8;
        #pragma unroll
        for (int j = 0; j < 4; j++) {
            int col = nBase + wn * 32 + j * 8 + 2 * c;
            float2 bv = *reinterpret_cast<const float2*>(biasP + col);
            float v00 = acc[i][j][0] + bv.x;
            float v01 = acc[i][j][1] + bv.y;
            float v10 = acc[i][j][2] + bv.x;
            float v11 = acc[i][j][3] + bv.y;
            if (MODE == 0) {
                *reinterpret_cast<float2*>(g_pre + (size_t)r0 * DIM + col) = make_float2(v00, v01);
                *reinterpret_cast<float2*>(g_pre + (size_t)r1 * DIM + col) = make_float2(v10, v11);
            } else if (MODE == 1) {
                if (r0 < M)
                    *reinterpret_cast<float2*>(g_h1 + (size_t)(obase + r0) * HID + col) =
                        make_float2(gelu_t(v00), gelu_t(v01));
                if (r1 < M)
                    *reinterpret_cast<float2*>(g_h1 + (size_t)(obase + r1) * HID + col) =
                        make_float2(gelu_t(v10), gelu_t(v11));
            } else {
                if (r0 < M) {
                    float gt = g_gatev[e * NCAP + r0];
                    int dst  = g_tokslot[e * NCAP + r0];
                    *reinterpret_cast<float2*>(g_contrib + (size_t)dst * DIM + col) =
                        make_float2(v00 * gt, v01 * gt);
                }
                if (r1 < M) {
                    float gt = g_gatev[e * NCAP + r1];
                    int dst  = g_tokslot[e * NCAP + r1];
                    *reinterpret_cast<float2*>(g_contrib + (size_t)dst * DIM + col) =
                        make_float2(v10 * gt, v11 * gt);
                }
            }
        }
    }
}

// ---------------------------------------------------------------------------
// LayerNorm of g_pre -> g_hidden
// ---------------------------------------------------------------------------
__global__ void __launch_bounds__(256) ln1_k(const float* __restrict__ gw,
                                             const float* __restrict__ bw) {
    int row = blockIdx.x, t = threadIdx.x;
    float4 v = reinterpret_cast<const float4*>(g_pre + (size_t)row * DIM)[t];
    float s = v.x + v.y + v.z + v.w;
    float q = v.x * v.x + v.y * v.y + v.z * v.z + v.w * v.w;
    float mu, rs;
    row_stats1024(s, q, mu, rs);
    float4 gg = reinterpret_cast<const float4*>(gw)[t];
    float4 bb = reinterpret_cast<const float4*>(bw)[t];
    float4 o;
    o.x = (v.x - mu) * rs * gg.x + bb.x;
    o.y = (v.y - mu) * rs * gg.y + bb.y;
    o.z = (v.z - mu) * rs * gg.z + bb.z;
    o.w = (v.w - mu) * rs * gg.w + bb.w;
    reinterpret_cast<float4*>(g_hidden + (size_t)row * DIM)[t] = o;
}

// ---------------------------------------------------------------------------
// Router: one warp per token. logits = hidden @ Wg; top-2 softmax renorm.
// ---------------------------------------------------------------------------
__global__ void __launch_bounds__(256) router_k(const float* __restrict__ Wg) {
    int tok  = blockIdx.x * 8 + (threadIdx.x >> 5);
    int lane = threadIdx.x & 31;
    const float4* h4 = reinterpret_cast<const float4*>(g_hidden + (size_t)tok * DIM);
    float a[8];
    #pragma unroll
    for (int ci = 0; ci < 8; ci++) a[ci] = 0.f;
    for (int t = lane; t < DIM / 4; t += 32) {
        float4 h = h4[t];
        const float* wr = Wg + (size_t)t * 4 * NE;
        #pragma unroll
        for (int u = 0; u < 4; u++) {
            float hv = (u == 0) ? h.x : (u == 1) ? h.y : (u == 2) ? h.z : h.w;
            float4 w0 = reinterpret_cast<const float4*>(wr + u * NE)[0];
            float4 w1 = reinterpret_cast<const float4*>(wr + u * NE)[1];
            a[0] += hv * w0.x; a[1] += hv * w0.y; a[2] += hv * w0.z; a[3] += hv * w0.w;
            a[4] += hv * w1.x; a[5] += hv * w1.y; a[6] += hv * w1.z; a[7] += hv * w1.w;
        }
    }
    #pragma unroll
    for (int ci = 0; ci < 8; ci++)
        #pragma unroll
        for (int o = 16; o; o >>= 1) a[ci] += __shfl_xor_sync(0xffffffffu, a[ci], o);
    if (lane == 0) {
        int bi = 0; float bv = a[0];
        #pragma unroll
        for (int ci = 1; ci < 8; ci++) if (a[ci] > bv) { bv = a[ci]; bi = ci; }
        int si = -1; float sv = -3.4e38f;
        #pragma unroll
        for (int ci = 0; ci < 8; ci++)
            if (ci != bi && a[ci] > sv) { sv = a[ci]; si = ci; }
        // renormalized top-2 softmax gates
        float p0 = 1.f / (1.f + expf(sv - bv));
        float p1 = 1.f - p0;
        int pos = atomicAdd(&g_cnt[bi], 1);
        g_list[bi * NCAP + pos] = tok;
        g_gatev[bi * NCAP + pos] = p0;
        g_tokslot[bi * NCAP + pos] = tok * 2;
        pos = atomicAdd(&g_cnt[si], 1);
        g_list[si * NCAP + pos] = tok;
        g_gatev[si * NCAP + pos] = p1;
        g_tokslot[si * NCAP + pos] = tok * 2 + 1;
    }
}

__global__ void zero_k() {
    if (threadIdx.x < NE) g_cnt[threadIdx.x] = 0;
}

__global__ void scan_k() {
    if (threadIdx.x == 0) {
        int s = 0;
        for (int e = 0; e < NE; e++) { g_off[e] = s; s += g_cnt[e]; }
    }
}

// ---------------------------------------------------------------------------
// Combine: y = hidden + c0 + c1; LN(g_moe); LN(g_out) -> g_final
// ---------------------------------------------------------------------------
__global__ void __launch_bounds__(256) combine_k(const float* __restrict__ gm,
                                                 const float* __restrict__ bm,
                                                 const float* __restrict__ go,
                                                 const float* __restrict__ bo) {
    int row = blockIdx.x, t = threadIdx.x;
    float4 v  = reinterpret_cast<const float4*>(g_hidden + (size_t)row * DIM)[t];
    float4 c0 = reinterpret_cast<const float4*>(g_contrib + (size_t)(2 * row) * DIM)[t];
    float4 c1 = reinterpret_cast<const float4*>(g_contrib + (size_t)(2 * row + 1) * DIM)[t];
    v.x += c0.x + c1.x; v.y += c0.y + c1.y; v.z += c0.z + c1.z; v.w += c0.w + c1.w;

    float s = v.x + v.y + v.z + v.w;
    float q = v.x * v.x + v.y * v.y + v.z * v.z + v.w * v.w;
    float mu, rs;
    row_stats1024(s, q, mu, rs);
    float4 g1 = reinterpret_cast<const float4*>(gm)[t];
    float4 b1 = reinterpret_cast<const float4*>(bm)[t];
    float4 y;
    y.x = (v.x - mu) * rs * g1.x + b1.x;
    y.y = (v.y - mu) * rs * g1.y + b1.y;
    y.z = (v.z - mu) * rs * g1.z + b1.z;
    y.w = (v.w - mu) * rs * g1.w + b1.w;

    s = y.x + y.y + y.z + y.w;
    q = y.x * y.x + y.y * y.y + y.z * y.z + y.w * y.w;
    float mu2, rs2;
    row_stats1024(s, q, mu2, rs2);
    float4 g2 = reinterpret_cast<const float4*>(go)[t];
    float4 b2 = reinterpret_cast<const float4*>(bo)[t];
    float4 o;
    o.x = (y.x - mu2) * rs2 * g2.x + b2.x;
    o.y = (y.y - mu2) * rs2 * g2.y + b2.y;
    o.z = (y.z - mu2) * rs2 * g2.z + b2.z;
    o.w = (y.w - mu2) * rs2 * g2.w + b2.w;
    reinterpret_cast<float4*>(g_final + (size_t)row * DIM)[t] = o;
}

// ---------------------------------------------------------------------------
// Classifier: one warp per token, out[tok, 0..7] = final @ Wc + bc
// ---------------------------------------------------------------------------
__global__ void __launch_bounds__(256) cls_k(const float* __restrict__ Wc,
                                             const float* __restrict__ bc,
                                             float* __restrict__ out) {
    int tok  = blockIdx.x * 8 + (threadIdx.x >> 5);
    int lane = threadIdx.x & 31;
    const float4* h4 = reinterpret_cast<const float4*>(g_final + (size_t)tok * DIM);
    float a[8];
    #pragma unroll
    for (int ci = 0; ci < 8; ci++) a[ci] = 0.f;
    for (int t = lane; t < DIM / 4; t += 32) {
        float4 h = h4[t];
        const float* wr = Wc + (size_t)t * 4 * NC;
        #pragma unroll
        for (int u = 0; u < 4; u++) {
            float hv = (u == 0) ? h.x : (u == 1) ? h.y : (u == 2) ? h.z : h.w;
            float4 w0 = reinterpret_cast<const float4*>(wr + u * NC)[0];
            float4 w1 = reinterpret_cast<const float4*>(wr + u * NC)[1];
            a[0] += hv * w0.x; a[1] += hv * w0.y; a[2] += hv * w0.z; a[3] += hv * w0.w;
            a[4] += hv * w1.x; a[5] += hv * w1.y; a[6] += hv * w1.z; a[7] += hv * w1.w;
        }
    }
    #pragma unroll
    for (int ci = 0; ci < 8; ci++)
        #pragma unroll
        for (int o = 16; o; o >>= 1) a[ci] += __shfl_xor_sync(0xffffffffu, a[ci], o);
    if (lane == 0) {
        #pragma unroll
        for (int ci = 0; ci < 8; ci++)
            out[(size_t)tok * NC + ci] = a[ci] + bc[ci];
    }
}

// ---------------------------------------------------------------------------
// Entry point
// ---------------------------------------------------------------------------
extern "C" void kernel_launch(void* const* d_in, const int* in_sizes, int n_in,
                              void* d_out, int out_size) {
    (void)in_sizes; (void)n_in; (void)out_size;
    const float* x    = (const float*)d_in[0];
    const float* Wp   = (const float*)d_in[1];
    const float* bp   = (const float*)d_in[2];
    const float* gin  = (const float*)d_in[3];
    const float* bin  = (const float*)d_in[4];
    const float* Wg   = (const float*)d_in[5];
    const float* W1   = (const float*)d_in[6];
    const float* b1   = (const float*)d_in[7];
    const float* W2   = (const float*)d_in[8];
    const float* b2   = (const float*)d_in[9];
    const float* gmoe = (const float*)d_in[10];
    const float* bmoe = (const float*)d_in[11];
    const float* gout = (const float*)d_in[12];
    const float* bout = (const float*)d_in[13];
    const float* Wc   = (const float*)d_in[14];
    const float* bc   = (const float*)d_in[15];
    float* out = (float*)d_out;

    cudaFuncSetAttribute((const void*)gemm_tpl<0>,
                         cudaFuncAttributeMaxDynamicSharedMemorySize, SMEM_BYTES);
    cudaFuncSetAttribute((const void*)gemm_tpl<1>,
                         cudaFuncAttributeMaxDynamicSharedMemorySize, SMEM_BYTES);
    cudaFuncSetAttribute((const void*)gemm_tpl<2>,
                         cudaFuncAttributeMaxDynamicSharedMemorySize, SMEM_BYTES);

    // 1. pre = x @ Wp + bp
    gemm_tpl<0><<<dim3(DIM / BN, NTOK / BM, 1), 256, SMEM_BYTES>>>(x, Wp, bp, DIM, DIM, DIM);
    // 2. hidden = LN(pre)
    ln1_k<<<NTOK, 256>>>(gin, bin);
    // 3. routing
    zero_k<<<1, 32>>>();
    router_k<<<NTOK / 8, 256>>>(Wg);
    scan_k<<<1, 32>>>();
    // 4. expert FFN (routed-sparse, 2N ragged rows)
    gemm_tpl<1><<<dim3(HID / BN, NTOK / BM, NE), 256, SMEM_BYTES>>>(nullptr, W1, b1, DIM, HID, DIM);
    gemm_tpl<2><<<dim3(DIM / BN, NTOK / BM, NE), 256, SMEM_BYTES>>>(nullptr, W2, b2, HID, DIM, HID);
    // 5. combine + double LN
    combine_k<<<NTOK, 256>>>(gmoe, bmoe, gout, bout);
    // 6. classifier
    cls_k<<<NTOK / 8, 256>>>(Wc, bc, out);
}

// round 7
// speedup vs baseline: 1.3974x; 1.3974x over previous
#include <cuda_runtime.h>
#include <cstdint>

// ---------------------------------------------------------------------------
// Problem constants
// ---------------------------------------------------------------------------
constexpr int NTOK = 8192;
constexpr int DIM  = 1024;
constexpr int HID  = 4096;
constexpr int NE   = 8;
constexpr int NC   = 8;
constexpr int NCAP = 8192;

// GEMM tile config
constexpr int BM = 128, BN = 128, BK = 32;
// stride mod 16 == 4 -> (2*stride) mod 32 == 8 -> fragment banks c*8+g, all distinct
constexpr int SA_STRIDE = BM + 4;   // 132
constexpr int SB_STRIDE = BN + 4;   // 132
constexpr int SMEM_BYTES = (2 * BK * SA_STRIDE + 2 * BK * SB_STRIDE) * 4; // 67584

// ---------------------------------------------------------------------------
// Device scratch
// ---------------------------------------------------------------------------
__device__ float g_pre[(size_t)NTOK * DIM];
__device__ float g_hidden[(size_t)NTOK * DIM];
__device__ float g_h1[(size_t)2 * NTOK * HID];
__device__ float g_contrib[(size_t)2 * NTOK * DIM];
__device__ float g_final[(size_t)NTOK * DIM];
__device__ int   g_cnt[NE];
__device__ int   g_off[NE];
__device__ int   g_list[NE * NCAP];
__device__ int   g_tokslot[NE * NCAP];
__device__ float g_gatev[NE * NCAP];

// ---------------------------------------------------------------------------
// Helpers
// ---------------------------------------------------------------------------
// Pack 2 floats into bf16x2 (lo half = x0, hi half = x1); residual pair -> lo.
__device__ __forceinline__ uint32_t pack_split(float x0, float x1, uint32_t& lo) {
    uint32_t h;
    asm("cvt.rn.bf16x2.f32 %0, %1, %2;" : "=r"(h) : "f"(x1), "f"(x0));
    float h0 = __uint_as_float(h << 16);          // bf16(x0) as f32
    float h1 = __uint_as_float(h & 0xFFFF0000u);  // bf16(x1) as f32
    asm("cvt.rn.bf16x2.f32 %0, %1, %2;" : "=r"(lo) : "f"(x1 - h1), "f"(x0 - h0));
    return h;
}

__device__ __forceinline__ void mma_bf16(float* d, const uint32_t* a, const uint32_t* b) {
    asm volatile(
        "mma.sync.aligned.m16n8k16.row.col.f32.bf16.bf16.f32 "
        "{%0,%1,%2,%3}, {%4,%5,%6,%7}, {%8,%9}, {%0,%1,%2,%3};\n"
        : "+f"(d[0]), "+f"(d[1]), "+f"(d[2]), "+f"(d[3])
        : "r"(a[0]), "r"(a[1]), "r"(a[2]), "r"(a[3]), "r"(b[0]), "r"(b[1]));
}

__device__ __forceinline__ float gelu_t(float x) {
    return 0.5f * x * (1.f + tanhf(0.7978845608028654f * (x + 0.044715f * x * x * x)));
}

__device__ __forceinline__ void row_stats1024(float s, float q, float& mu, float& rstd) {
    __shared__ float shs[8], shq[8];
    #pragma unroll
    for (int o = 16; o; o >>= 1) {
        s += __shfl_xor_sync(0xffffffffu, s, o);
        q += __shfl_xor_sync(0xffffffffu, q, o);
    }
    int w = threadIdx.x >> 5;
    __syncthreads();
    if ((threadIdx.x & 31) == 0) { shs[w] = s; shq[w] = q; }
    __syncthreads();
    float ts = 0.f, tq = 0.f;
    #pragma unroll
    for (int k = 0; k < 8; k++) { ts += shs[k]; tq += shq[k]; }
    mu = ts * (1.f / DIM);
    float var = tq * (1.f / DIM) - mu * mu;
    rstd = rsqrtf(var + 1e-5f);
}

// ---------------------------------------------------------------------------
// Core tiled GEMM, fp32-accurate via 3x bf16 compensation at m16n8k16:
//   a*b ~= a_lo*b_hi + a_hi*b_lo + a_hi*b_hi
// ---------------------------------------------------------------------------
template <int MODE>
__global__ void __launch_bounds__(256)
gemm_tpl(const float* __restrict__ A, const float* __restrict__ Bmat,
         const float* __restrict__ bias, int K, int Nw, int ldA) {
    extern __shared__ float smem[];
    float* sA = smem;
    float* sB = smem + 2 * BK * SA_STRIDE;

    const int e = blockIdx.z;
    int M;
    const float* Ap;
    const int* ridx = nullptr;
    int obase = 0;
    if (MODE == 0) {
        M = NTOK; Ap = A;
    } else if (MODE == 1) {
        M = g_cnt[e]; Ap = g_hidden; ridx = g_list + e * NCAP; obase = g_off[e];
    } else {
        M = g_cnt[e]; Ap = g_h1 + (size_t)g_off[e] * HID;
    }
    if ((int)blockIdx.y * BM >= M) return;

    const float* Bp    = Bmat + (size_t)e * K * Nw;
    const float* biasP = bias + (size_t)e * Nw;

    const int tid  = threadIdx.x;
    const int lane = tid & 31, warp = tid >> 5;
    const int wm = warp & 1, wn = warp >> 1;
    const int g = lane >> 2, c = lane & 3;
    const int mBase = blockIdx.y * BM;
    const int nBase = blockIdx.x * BN;

    float acc[4][4][4];
    #pragma unroll
    for (int i = 0; i < 4; i++)
        #pragma unroll
        for (int j = 0; j < 4; j++)
            #pragma unroll
            for (int k = 0; k < 4; k++) acc[i][j][k] = 0.f;

    float4 ar[4], br[4];

    auto LOADT = [&](int kt) {
        const int ka = kt * BK + warp * 4;
        #pragma unroll
        for (int p = 0; p < 4; p++) {
            int mg = mBase + lane + 32 * p;
            float4 v = make_float4(0.f, 0.f, 0.f, 0.f);
            if (mg < M) {
                int row = (MODE == 1) ? ridx[mg] : mg;
                v = *reinterpret_cast<const float4*>(Ap + (size_t)row * ldA + ka);
            }
            ar[p] = v;
        }
        const int kb = kt * BK + warp;
        #pragma unroll
        for (int p = 0; p < 4; p++)
            br[p] = *reinterpret_cast<const float4*>(
                Bp + (size_t)(kb + 8 * p) * Nw + nBase + lane * 4);
    };

    auto STORET = [&](int buf) {
        float* a0 = sA + buf * BK * SA_STRIDE;
        #pragma unroll
        for (int p = 0; p < 4; p++) {
            int ml = lane + 32 * p;
            a0[(warp * 4 + 0) * SA_STRIDE + ml] = ar[p].x;
            a0[(warp * 4 + 1) * SA_STRIDE + ml] = ar[p].y;
            a0[(warp * 4 + 2) * SA_STRIDE + ml] = ar[p].z;
            a0[(warp * 4 + 3) * SA_STRIDE + ml] = ar[p].w;
        }
        float* b0 = sB + buf * BK * SB_STRIDE;
        #pragma unroll
        for (int p = 0; p < 4; p++)
            *reinterpret_cast<float4*>(b0 + (warp + 8 * p) * SB_STRIDE + lane * 4) = br[p];
    };

    const int nkt = K / BK;
    LOADT(0);
    STORET(0);
    __syncthreads();

    for (int kt = 0; kt < nkt; kt++) {
        if (kt + 1 < nkt) LOADT(kt + 1);
        const int cur = kt & 1;
        const float* a0 = sA + cur * BK * SA_STRIDE;
        const float* b0 = sB + cur * BK * SB_STRIDE;
        #pragma unroll
        for (int ks = 0; ks < 2; ks++) {          // two k16 slices per BK=32
            const int k0 = ks * 16 + c * 2;
            uint32_t ah[4][4], al[4][4], bh[4][2], bl[4][2];
            #pragma unroll
            for (int i = 0; i < 4; i++) {
                int m = wm * 64 + i * 16 + g;
                float f00 = a0[(k0 + 0) * SA_STRIDE + m];
                float f01 = a0[(k0 + 1) * SA_STRIDE + m];
                float f10 = a0[(k0 + 0) * SA_STRIDE + m + 8];
                float f11 = a0[(k0 + 1) * SA_STRIDE + m + 8];
                float f20 = a0[(k0 + 8) * SA_STRIDE + m];
                float f21 = a0[(k0 + 9) * SA_STRIDE + m];
                float f30 = a0[(k0 + 8) * SA_STRIDE + m + 8];
                float f31 = a0[(k0 + 9) * SA_STRIDE + m + 8];
                ah[i][0] = pack_split(f00, f01, al[i][0]);
                ah[i][1] = pack_split(f10, f11, al[i][1]);
                ah[i][2] = pack_split(f20, f21, al[i][2]);
                ah[i][3] = pack_split(f30, f31, al[i][3]);
            }
            #pragma unroll
            for (int j = 0; j < 4; j++) {
                int n = wn * 32 + j * 8 + g;
                float g00 = b0[(k0 + 0) * SB_STRIDE + n];
                float g01 = b0[(k0 + 1) * SB_STRIDE + n];
                float g10 = b0[(k0 + 8) * SB_STRIDE + n];
                float g11 = b0[(k0 + 9) * SB_STRIDE + n];
                bh[j][0] = pack_split(g00, g01, bl[j][0]);
                bh[j][1] = pack_split(g10, g11, bl[j][1]);
            }
            #pragma unroll
            for (int i = 0; i < 4; i++)
                #pragma unroll
                for (int j = 0; j < 4; j++)
                    mma_bf16(acc[i][j], al[i], bh[j]);
            #pragma unroll
            for (int i = 0; i < 4; i++)
                #pragma unroll
                for (int j = 0; j < 4; j++)
                    mma_bf16(acc[i][j], ah[i], bl[j]);
            #pragma unroll
            for (int i = 0; i < 4; i++)
                #pragma unroll
                for (int j = 0; j < 4; j++)
                    mma_bf16(acc[i][j], ah[i], bh[j]);
        }
        if (kt + 1 < nkt) STORET((kt + 1) & 1);   // other buffer: safe pre-sync
        __syncthreads();
    }

    // Epilogue (D frag layout identical to the tf32 m16n8k8 path)
    #pragma unroll
    for (int i = 0; i < 4; i++) {
        int r0 = mBase + wm * 64 + i * 16 + g;
        int r1 = r0 + 8;
        #pragma unroll
        for (int j = 0; j < 4; j++) {
            int col = nBase + wn * 32 + j * 8 + 2 * c;
            float2 bv = *reinterpret_cast<const float2*>(biasP + col);
            float v00 = acc[i][j][0] + bv.x;
            float v01 = acc[i][j][1] + bv.y;
            float v10 = acc[i][j][2] + bv.x;
            float v11 = acc[i][j][3] + bv.y;
            if (MODE == 0) {
                *reinterpret_cast<float2*>(g_pre + (size_t)r0 * DIM + col) = make_float2(v00, v01);
                *reinterpret_cast<float2*>(g_pre + (size_t)r1 * DIM + col) = make_float2(v10, v11);
            } else if (MODE == 1) {
                if (r0 < M)
                    *reinterpret_cast<float2*>(g_h1 + (size_t)(obase + r0) * HID + col) =
                        make_float2(gelu_t(v00), gelu_t(v01));
                if (r1 < M)
                    *reinterpret_cast<float2*>(g_h1 + (size_t)(obase + r1) * HID + col) =
                        make_float2(gelu_t(v10), gelu_t(v11));
            } else {
                if (r0 < M) {
                    float gt = g_gatev[e * NCAP + r0];
                    int dst  = g_tokslot[e * NCAP + r0];
                    *reinterpret_cast<float2*>(g_contrib + (size_t)dst * DIM + col) =
                        make_float2(v00 * gt, v01 * gt);
                }
                if (r1 < M) {
                    float gt = g_gatev[e * NCAP + r1];
                    int dst  = g_tokslot[e * NCAP + r1];
                    *reinterpret_cast<float2*>(g_contrib + (size_t)dst * DIM + col) =
                        make_float2(v10 * gt, v11 * gt);
                }
            }
        }
    }
}

// ---------------------------------------------------------------------------
// LayerNorm of g_pre -> g_hidden
// ---------------------------------------------------------------------------
__global__ void __launch_bounds__(256) ln1_k(const float* __restrict__ gw,
                                             const float* __restrict__ bw) {
    int row = blockIdx.x, t = threadIdx.x;
    float4 v = reinterpret_cast<const float4*>(g_pre + (size_t)row * DIM)[t];
    float s = v.x + v.y + v.z + v.w;
    float q = v.x * v.x + v.y * v.y + v.z * v.z + v.w * v.w;
    float mu, rs;
    row_stats1024(s, q, mu, rs);
    float4 gg = reinterpret_cast<const float4*>(gw)[t];
    float4 bb = reinterpret_cast<const float4*>(bw)[t];
    float4 o;
    o.x = (v.x - mu) * rs * gg.x + bb.x;
    o.y = (v.y - mu) * rs * gg.y + bb.y;
    o.z = (v.z - mu) * rs * gg.z + bb.z;
    o.w = (v.w - mu) * rs * gg.w + bb.w;
    reinterpret_cast<float4*>(g_hidden + (size_t)row * DIM)[t] = o;
}

// ---------------------------------------------------------------------------
// Router
// ---------------------------------------------------------------------------
__global__ void __launch_bounds__(256) router_k(const float* __restrict__ Wg) {
    int tok  = blockIdx.x * 8 + (threadIdx.x >> 5);
    int lane = threadIdx.x & 31;
    const float4* h4 = reinterpret_cast<const float4*>(g_hidden + (size_t)tok * DIM);
    float a[8];
    #pragma unroll
    for (int ci = 0; ci < 8; ci++) a[ci] = 0.f;
    for (int t = lane; t < DIM / 4; t += 32) {
        float4 h = h4[t];
        const float* wr = Wg + (size_t)t * 4 * NE;
        #pragma unroll
        for (int u = 0; u < 4; u++) {
            float hv = (u == 0) ? h.x : (u == 1) ? h.y : (u == 2) ? h.z : h.w;
            float4 w0 = reinterpret_cast<const float4*>(wr + u * NE)[0];
            float4 w1 = reinterpret_cast<const float4*>(wr + u * NE)[1];
            a[0] += hv * w0.x; a[1] += hv * w0.y; a[2] += hv * w0.z; a[3] += hv * w0.w;
            a[4] += hv * w1.x; a[5] += hv * w1.y; a[6] += hv * w1.z; a[7] += hv * w1.w;
        }
    }
    #pragma unroll
    for (int ci = 0; ci < 8; ci++)
        #pragma unroll
        for (int o = 16; o; o >>= 1) a[ci] += __shfl_xor_sync(0xffffffffu, a[ci], o);
    if (lane == 0) {
        int bi = 0; float bv = a[0];
        #pragma unroll
        for (int ci = 1; ci < 8; ci++) if (a[ci] > bv) { bv = a[ci]; bi = ci; }
        int si = -1; float sv = -3.4e38f;
        #pragma unroll
        for (int ci = 0; ci < 8; ci++)
            if (ci != bi && a[ci] > sv) { sv = a[ci]; si = ci; }
        if (si < 0) si = (bi + 1) & 7;   // NaN-safe fallback, keeps indices in range
        float p0 = 1.f / (1.f + expf(sv - bv));
        float p1 = 1.f - p0;
        int pos = atomicAdd(&g_cnt[bi], 1);
        g_list[bi * NCAP + pos] = tok;
        g_gatev[bi * NCAP + pos] = p0;
        g_tokslot[bi * NCAP + pos] = tok * 2;
        pos = atomicAdd(&g_cnt[si], 1);
        g_list[si * NCAP + pos] = tok;
        g_gatev[si * NCAP + pos] = p1;
        g_tokslot[si * NCAP + pos] = tok * 2 + 1;
    }
}

__global__ void zero_k() {
    if (threadIdx.x < NE) g_cnt[threadIdx.x] = 0;
}

__global__ void scan_k() {
    if (threadIdx.x == 0) {
        int s = 0;
        for (int e = 0; e < NE; e++) { g_off[e] = s; s += g_cnt[e]; }
    }
}

// ---------------------------------------------------------------------------
// Combine + double LN
// ---------------------------------------------------------------------------
__global__ void __launch_bounds__(256) combine_k(const float* __restrict__ gm,
                                                 const float* __restrict__ bm,
                                                 const float* __restrict__ go,
                                                 const float* __restrict__ bo) {
    int row = blockIdx.x, t = threadIdx.x;
    float4 v  = reinterpret_cast<const float4*>(g_hidden + (size_t)row * DIM)[t];
    float4 c0 = reinterpret_cast<const float4*>(g_contrib + (size_t)(2 * row) * DIM)[t];
    float4 c1 = reinterpret_cast<const float4*>(g_contrib + (size_t)(2 * row + 1) * DIM)[t];
    v.x += c0.x + c1.x; v.y += c0.y + c1.y; v.z += c0.z + c1.z; v.w += c0.w + c1.w;
    float s = v.x + v.y + v.z + v.w;
    float q = v.x * v.x + v.y * v.y + v.z * v.z + v.w * v.w;
    float mu, rs;
    row_stats1024(s, q, mu, rs);
    float4 g1 = reinterpret_cast<const float4*>(gm)[t];
    float4 b1 = reinterpret_cast<const float4*>(bm)[t];
    float4 y;
    y.x = (v.x - mu) * rs * g1.x + b1.x;
    y.y = (v.y - mu) * rs * g1.y + b1.y;
    y.z = (v.z - mu) * rs * g1.z + b1.z;
    y.w = (v.w - mu) * rs * g1.w + b1.w;
    s = y.x + y.y + y.z + y.w;
    q = y.x * y.x + y.y * y.y + y.z * y.z + y.w * y.w;
    float mu2, rs2;
    row_stats1024(s, q, mu2, rs2);
    float4 g2 = reinterpret_cast<const float4*>(go)[t];
    float4 b2 = reinterpret_cast<const float4*>(bo)[t];
    float4 o;
    o.x = (y.x - mu2) * rs2 * g2.x + b2.x;
    o.y = (y.y - mu2) * rs2 * g2.y + b2.y;
    o.z = (y.z - mu2) * rs2 * g2.z + b2.z;
    o.w = (y.w - mu2) * rs2 * g2.w + b2.w;
    reinterpret_cast<float4*>(g_final + (size_t)row * DIM)[t] = o;
}

// ---------------------------------------------------------------------------
// Classifier
// ---------------------------------------------------------------------------
__global__ void __launch_bounds__(256) cls_k(const float* __restrict__ Wc,
                                             const float* __restrict__ bc,
                                             float* __restrict__ out) {
    int tok  = blockIdx.x * 8 + (threadIdx.x >> 5);
    int lane = threadIdx.x & 31;
    const float4* h4 = reinterpret_cast<const float4*>(g_final + (size_t)tok * DIM);
    float a[8];
    #pragma unroll
    for (int ci = 0; ci < 8; ci++) a[ci] = 0.f;
    for (int t = lane; t < DIM / 4; t += 32) {
        float4 h = h4[t];
        const float* wr = Wc + (size_t)t * 4 * NC;
        #pragma unroll
        for (int u = 0; u < 4; u++) {
            float hv = (u == 0) ? h.x : (u == 1) ? h.y : (u == 2) ? h.z : h.w;
            float4 w0 = reinterpret_cast<const float4*>(wr + u * NC)[0];
            float4 w1 = reinterpret_cast<const float4*>(wr + u * NC)[1];
            a[0] += hv * w0.x; a[1] += hv * w0.y; a[2] += hv * w0.z; a[3] += hv * w0.w;
            a[4] += hv * w1.x; a[5] += hv * w1.y; a[6] += hv * w1.z; a[7] += hv * w1.w;
        }
    }
    #pragma unroll
    for (int ci = 0; ci < 8; ci++)
        #pragma unroll
        for (int o = 16; o; o >>= 1) a[ci] += __shfl_xor_sync(0xffffffffu, a[ci], o);
    if (lane == 0) {
        #pragma unroll
        for (int ci = 0; ci < 8; ci++)
            out[(size_t)tok * NC + ci] = a[ci] + bc[ci];
    }
}

// ---------------------------------------------------------------------------
// Entry point
// ---------------------------------------------------------------------------
extern "C" void kernel_launch(void* const* d_in, const int* in_sizes, int n_in,
                              void* d_out, int out_size) {
    (void)in_sizes; (void)n_in; (void)out_size;
    const float* x    = (const float*)d_in[0];
    const float* Wp   = (const float*)d_in[1];
    const float* bp   = (const float*)d_in[2];
    const float* gin  = (const float*)d_in[3];
    const float* bin  = (const float*)d_in[4];
    const float* Wg   = (const float*)d_in[5];
    const float* W1   = (const float*)d_in[6];
    const float* b1   = (const float*)d_in[7];
    const float* W2   = (const float*)d_in[8];
    const float* b2   = (const float*)d_in[9];
    const float* gmoe = (const float*)d_in[10];
    const float* bmoe = (const float*)d_in[11];
    const float* gout = (const float*)d_in[12];
    const float* bout = (const float*)d_in[13];
    const float* Wc   = (const float*)d_in[14];
    const float* bc   = (const float*)d_in[15];
    float* out = (float*)d_out;

    cudaFuncSetAttribute((const void*)gemm_tpl<0>,
                         cudaFuncAttributeMaxDynamicSharedMemorySize, SMEM_BYTES);
    cudaFuncSetAttribute((const void*)gemm_tpl<1>,
                         cudaFuncAttributeMaxDynamicSharedMemorySize, SMEM_BYTES);
    cudaFuncSetAttribute((const void*)gemm_tpl<2>,
                         cudaFuncAttributeMaxDynamicSharedMemorySize, SMEM_BYTES);

    gemm_tpl<0><<<dim3(DIM / BN, NTOK / BM, 1), 256, SMEM_BYTES>>>(x, Wp, bp, DIM, DIM, DIM);
    ln1_k<<<NTOK, 256>>>(gin, bin);
    zero_k<<<1, 32>>>();
    router_k<<<NTOK / 8, 256>>>(Wg);
    scan_k<<<1, 32>>>();
    gemm_tpl<1><<<dim3(HID / BN, NTOK / BM, NE), 256, SMEM_BYTES>>>(nullptr, W1, b1, DIM, HID, DIM);
    gemm_tpl<2><<<dim3(DIM / BN, NTOK / BM, NE), 256, SMEM_BYTES>>>(nullptr, W2, b2, HID, DIM, HID);
    combine_k<<<NTOK, 256>>>(gmoe, bmoe, gout, bout);
    cls_k<<<NTOK / 8, 256>>>(Wc, bc, out);
}

// round 8
// speedup vs baseline: 1.4350x; 1.0269x over previous
#include <cuda_runtime.h>
#include <cstdint>

// ---------------------------------------------------------------------------
// Problem constants
// ---------------------------------------------------------------------------
constexpr int NTOK = 8192;
constexpr int DIM  = 1024;
constexpr int HID  = 4096;
constexpr int NE   = 8;
constexpr int NC   = 8;
constexpr int NCAP = 8192;

// GEMM tile config
constexpr int BM = 128, BN = 128, BK = 32;
constexpr int KP   = BK / 2;        // 16 kpairs (bf16x2 along k)
constexpr int SSTR = 136;           // uint32 stride; 136 mod 32 == 8 -> banks 8c+g distinct
constexpr int ARR  = 2 * KP * SSTR; // one array, both buffers
constexpr int SMEM_BYTES = 4 * ARR * 4; // Ahi,Alo,Bhi,Blo = 69632 B

// ---------------------------------------------------------------------------
// Device scratch
// ---------------------------------------------------------------------------
__device__ float g_pre[(size_t)NTOK * DIM];
__device__ float g_hidden[(size_t)NTOK * DIM];
__device__ float g_h1[(size_t)2 * NTOK * HID];
__device__ float g_contrib[(size_t)2 * NTOK * DIM];
__device__ float g_final[(size_t)NTOK * DIM];
__device__ int   g_cnt[NE];
__device__ int   g_off[NE];
__device__ int   g_list[NE * NCAP];
__device__ int   g_tokslot[NE * NCAP];
__device__ float g_gatev[NE * NCAP];

// ---------------------------------------------------------------------------
// Helpers
// ---------------------------------------------------------------------------
// Pack 2 floats into bf16x2 (lo half = x0, hi half = x1); residual pair -> lo.
__device__ __forceinline__ uint32_t pack_split(float x0, float x1, uint32_t& lo) {
    uint32_t h;
    asm("cvt.rn.bf16x2.f32 %0, %1, %2;" : "=r"(h) : "f"(x1), "f"(x0));
    float h0 = __uint_as_float(h << 16);          // bf16(x0) as f32
    float h1 = __uint_as_float(h & 0xFFFF0000u);  // bf16(x1) as f32
    asm("cvt.rn.bf16x2.f32 %0, %1, %2;" : "=r"(lo) : "f"(x1 - h1), "f"(x0 - h0));
    return h;
}

__device__ __forceinline__ void mma_bf16(float* d, const uint32_t* a, const uint32_t* b) {
    asm volatile(
        "mma.sync.aligned.m16n8k16.row.col.f32.bf16.bf16.f32 "
        "{%0,%1,%2,%3}, {%4,%5,%6,%7}, {%8,%9}, {%0,%1,%2,%3};\n"
        : "+f"(d[0]), "+f"(d[1]), "+f"(d[2]), "+f"(d[3])
        : "r"(a[0]), "r"(a[1]), "r"(a[2]), "r"(a[3]), "r"(b[0]), "r"(b[1]));
}

__device__ __forceinline__ float gelu_t(float x) {
    return 0.5f * x * (1.f + tanhf(0.7978845608028654f * (x + 0.044715f * x * x * x)));
}

__device__ __forceinline__ void row_stats1024(float s, float q, float& mu, float& rstd) {
    __shared__ float shs[8], shq[8];
    #pragma unroll
    for (int o = 16; o; o >>= 1) {
        s += __shfl_xor_sync(0xffffffffu, s, o);
        q += __shfl_xor_sync(0xffffffffu, q, o);
    }
    int w = threadIdx.x >> 5;
    __syncthreads();
    if ((threadIdx.x & 31) == 0) { shs[w] = s; shq[w] = q; }
    __syncthreads();
    float ts = 0.f, tq = 0.f;
    #pragma unroll
    for (int k = 0; k < 8; k++) { ts += shs[k]; tq += shq[k]; }
    mu = ts * (1.f / DIM);
    float var = tq * (1.f / DIM) - mu * mu;
    rstd = rsqrtf(var + 1e-5f);
}

// ---------------------------------------------------------------------------
// Core tiled GEMM, fp32-accurate via 3x bf16 compensation at m16n8k16.
// smem holds pre-split bf16x2 operands: [kpair][row] for A, [kpair][col] for B.
// ---------------------------------------------------------------------------
template <int MODE>
__global__ void __launch_bounds__(256)
gemm_tpl(const float* __restrict__ A, const float* __restrict__ Bmat,
         const float* __restrict__ bias, int K, int Nw, int ldA) {
    extern __shared__ uint32_t smem[];
    uint32_t* sAhi = smem;
    uint32_t* sAlo = smem + ARR;
    uint32_t* sBhi = smem + 2 * ARR;
    uint32_t* sBlo = smem + 3 * ARR;

    const int e = blockIdx.z;
    int M;
    const float* Ap;
    const int* ridx = nullptr;
    int obase = 0;
    if (MODE == 0) {
        M = NTOK; Ap = A;
    } else if (MODE == 1) {
        M = g_cnt[e]; Ap = g_hidden; ridx = g_list + e * NCAP; obase = g_off[e];
    } else {
        M = g_cnt[e]; Ap = g_h1 + (size_t)g_off[e] * HID;
    }
    if ((int)blockIdx.y * BM >= M) return;

    const float* Bp    = Bmat + (size_t)e * K * Nw;
    const float* biasP = bias + (size_t)e * Nw;

    const int tid  = threadIdx.x;
    const int lane = tid & 31, warp = tid >> 5;
    const int wm = warp & 1, wn = warp >> 1;
    const int g = lane >> 2, c = lane & 3;
    const int mBase = blockIdx.y * BM;
    const int nBase = blockIdx.x * BN;

    // B staging assignment: kpair + 2 groups of 4 consecutive n
    const int bkp = tid >> 4;          // 0..15
    const int bn0 = (tid & 15) * 4;    // 0..60 (q adds +64)

    float acc[4][4][4];
    #pragma unroll
    for (int i = 0; i < 4; i++)
        #pragma unroll
        for (int j = 0; j < 4; j++)
            #pragma unroll
            for (int k = 0; k < 4; k++) acc[i][j][k] = 0.f;

    float4 ar[4], brE[2], brO[2];

    auto LOADT = [&](int kt) {
        const int ka = kt * BK + warp * 4;   // A: warp picks 4 consecutive k
        #pragma unroll
        for (int p = 0; p < 4; p++) {
            int mg = mBase + lane + 32 * p;
            float4 v = make_float4(0.f, 0.f, 0.f, 0.f);
            if (mg < M) {
                int row = (MODE == 1) ? ridx[mg] : mg;
                v = *reinterpret_cast<const float4*>(Ap + (size_t)row * ldA + ka);
            }
            ar[p] = v;
        }
        const int kb = kt * BK + 2 * bkp;    // B: thread owns kpair bkp
        #pragma unroll
        for (int q = 0; q < 2; q++) {
            const float* src = Bp + (size_t)kb * Nw + nBase + bn0 + q * 64;
            brE[q] = *reinterpret_cast<const float4*>(src);        // k even
            brO[q] = *reinterpret_cast<const float4*>(src + Nw);   // k odd
        }
    };

    auto STORET = [&](int buf) {
        uint32_t* aH = sAhi + buf * KP * SSTR;
        uint32_t* aL = sAlo + buf * KP * SSTR;
        uint32_t* bH = sBhi + buf * KP * SSTR;
        uint32_t* bL = sBlo + buf * KP * SSTR;
        #pragma unroll
        for (int p = 0; p < 4; p++) {
            int m = lane + 32 * p;
            uint32_t lo;
            uint32_t hi = pack_split(ar[p].x, ar[p].y, lo);   // kpair 2*warp
            aH[(2 * warp) * SSTR + m] = hi;
            aL[(2 * warp) * SSTR + m] = lo;
            hi = pack_split(ar[p].z, ar[p].w, lo);            // kpair 2*warp+1
            aH[(2 * warp + 1) * SSTR + m] = hi;
            aL[(2 * warp + 1) * SSTR + m] = lo;
        }
        #pragma unroll
        for (int q = 0; q < 2; q++) {
            uint4 h, l;
            h.x = pack_split(brE[q].x, brO[q].x, l.x);
            h.y = pack_split(brE[q].y, brO[q].y, l.y);
            h.z = pack_split(brE[q].z, brO[q].z, l.z);
            h.w = pack_split(brE[q].w, brO[q].w, l.w);
            *reinterpret_cast<uint4*>(bH + bkp * SSTR + bn0 + q * 64) = h;
            *reinterpret_cast<uint4*>(bL + bkp * SSTR + bn0 + q * 64) = l;
        }
    };

    const int nkt = K / BK;
    LOADT(0);
    STORET(0);
    __syncthreads();

    for (int kt = 0; kt < nkt; kt++) {
        if (kt + 1 < nkt) LOADT(kt + 1);
        const int cur = kt & 1;
        const uint32_t* aH = sAhi + cur * KP * SSTR;
        const uint32_t* aL = sAlo + cur * KP * SSTR;
        const uint32_t* bH = sBhi + cur * KP * SSTR;
        const uint32_t* bL = sBlo + cur * KP * SSTR;
        #pragma unroll
        for (int ks = 0; ks < 2; ks++) {
            const int kpc = ks * 8 + c;
            uint32_t ah[4][4], al[4][4], bh[4][2], bl[4][2];
            #pragma unroll
            for (int i = 0; i < 4; i++) {
                int m = wm * 64 + i * 16 + g;
                ah[i][0] = aH[kpc * SSTR + m];
                ah[i][1] = aH[kpc * SSTR + m + 8];
                ah[i][2] = aH[(kpc + 4) * SSTR + m];
                ah[i][3] = aH[(kpc + 4) * SSTR + m + 8];
                al[i][0] = aL[kpc * SSTR + m];
                al[i][1] = aL[kpc * SSTR + m + 8];
                al[i][2] = aL[(kpc + 4) * SSTR + m];
                al[i][3] = aL[(kpc + 4) * SSTR + m + 8];
            }
            #pragma unroll
            for (int j = 0; j < 4; j++) {
                int n = wn * 32 + j * 8 + g;
                bh[j][0] = bH[kpc * SSTR + n];
                bh[j][1] = bH[(kpc + 4) * SSTR + n];
                bl[j][0] = bL[kpc * SSTR + n];
                bl[j][1] = bL[(kpc + 4) * SSTR + n];
            }
            #pragma unroll
            for (int i = 0; i < 4; i++)
                #pragma unroll
                for (int j = 0; j < 4; j++)
                    mma_bf16(acc[i][j], al[i], bh[j]);
            #pragma unroll
            for (int i = 0; i < 4; i++)
                #pragma unroll
                for (int j = 0; j < 4; j++)
                    mma_bf16(acc[i][j], ah[i], bl[j]);
            #pragma unroll
            for (int i = 0; i < 4; i++)
                #pragma unroll
                for (int j = 0; j < 4; j++)
                    mma_bf16(acc[i][j], ah[i], bh[j]);
        }
        if (kt + 1 < nkt) STORET((kt + 1) & 1);   // other buffer: safe pre-sync
        __syncthreads();
    }

    // Epilogue (D frag layout unchanged)
    #pragma unroll
    for (int i = 0; i < 4; i++) {
        int r0 = mBase + wm * 64 + i * 16 + g;
        int r1 = r0 + 8;
        #pragma unroll
        for (int j = 0; j < 4; j++) {
            int col = nBase + wn * 32 + j * 8 + 2 * c;
            float2 bv = *reinterpret_cast<const float2*>(biasP + col);
            float v00 = acc[i][j][0] + bv.x;
            float v01 = acc[i][j][1] + bv.y;
            float v10 = acc[i][j][2] + bv.x;
            float v11 = acc[i][j][3] + bv.y;
            if (MODE == 0) {
                *reinterpret_cast<float2*>(g_pre + (size_t)r0 * DIM + col) = make_float2(v00, v01);
                *reinterpret_cast<float2*>(g_pre + (size_t)r1 * DIM + col) = make_float2(v10, v11);
            } else if (MODE == 1) {
                if (r0 < M)
                    *reinterpret_cast<float2*>(g_h1 + (size_t)(obase + r0) * HID + col) =
                        make_float2(gelu_t(v00), gelu_t(v01));
                if (r1 < M)
                    *reinterpret_cast<float2*>(g_h1 + (size_t)(obase + r1) * HID + col) =
                        make_float2(gelu_t(v10), gelu_t(v11));
            } else {
                if (r0 < M) {
                    float gt = g_gatev[e * NCAP + r0];
                    int dst  = g_tokslot[e * NCAP + r0];
                    *reinterpret_cast<float2*>(g_contrib + (size_t)dst * DIM + col) =
                        make_float2(v00 * gt, v01 * gt);
                }
                if (r1 < M) {
                    float gt = g_gatev[e * NCAP + r1];
                    int dst  = g_tokslot[e * NCAP + r1];
                    *reinterpret_cast<float2*>(g_contrib + (size_t)dst * DIM + col) =
                        make_float2(v10 * gt, v11 * gt);
                }
            }
        }
    }
}

// ---------------------------------------------------------------------------
// LayerNorm of g_pre -> g_hidden
// ---------------------------------------------------------------------------
__global__ void __launch_bounds__(256) ln1_k(const float* __restrict__ gw,
                                             const float* __restrict__ bw) {
    int row = blockIdx.x, t = threadIdx.x;
    float4 v = reinterpret_cast<const float4*>(g_pre + (size_t)row * DIM)[t];
    float s = v.x + v.y + v.z + v.w;
    float q = v.x * v.x + v.y * v.y + v.z * v.z + v.w * v.w;
    float mu, rs;
    row_stats1024(s, q, mu, rs);
    float4 gg = reinterpret_cast<const float4*>(gw)[t];
    float4 bb = reinterpret_cast<const float4*>(bw)[t];
    float4 o;
    o.x = (v.x - mu) * rs * gg.x + bb.x;
    o.y = (v.y - mu) * rs * gg.y + bb.y;
    o.z = (v.z - mu) * rs * gg.z + bb.z;
    o.w = (v.w - mu) * rs * gg.w + bb.w;
    reinterpret_cast<float4*>(g_hidden + (size_t)row * DIM)[t] = o;
}

// ---------------------------------------------------------------------------
// Router
// ---------------------------------------------------------------------------
__global__ void __launch_bounds__(256) router_k(const float* __restrict__ Wg) {
    int tok  = blockIdx.x * 8 + (threadIdx.x >> 5);
    int lane = threadIdx.x & 31;
    const float4* h4 = reinterpret_cast<const float4*>(g_hidden + (size_t)tok * DIM);
    float a[8];
    #pragma unroll
    for (int ci = 0; ci < 8; ci++) a[ci] = 0.f;
    for (int t = lane; t < DIM / 4; t += 32) {
        float4 h = h4[t];
        const float* wr = Wg + (size_t)t * 4 * NE;
        #pragma unroll
        for (int u = 0; u < 4; u++) {
            float hv = (u == 0) ? h.x : (u == 1) ? h.y : (u == 2) ? h.z : h.w;
            float4 w0 = reinterpret_cast<const float4*>(wr + u * NE)[0];
            float4 w1 = reinterpret_cast<const float4*>(wr + u * NE)[1];
            a[0] += hv * w0.x; a[1] += hv * w0.y; a[2] += hv * w0.z; a[3] += hv * w0.w;
            a[4] += hv * w1.x; a[5] += hv * w1.y; a[6] += hv * w1.z; a[7] += hv * w1.w;
        }
    }
    #pragma unroll
    for (int ci = 0; ci < 8; ci++)
        #pragma unroll
        for (int o = 16; o; o >>= 1) a[ci] += __shfl_xor_sync(0xffffffffu, a[ci], o);
    if (lane == 0) {
        int bi = 0; float bv = a[0];
        #pragma unroll
        for (int ci = 1; ci < 8; ci++) if (a[ci] > bv) { bv = a[ci]; bi = ci; }
        int si = -1; float sv = -3.4e38f;
        #pragma unroll
        for (int ci = 0; ci < 8; ci++)
            if (ci != bi && a[ci] > sv) { sv = a[ci]; si = ci; }
        if (si < 0) si = (bi + 1) & 7;   // NaN-safe fallback
        float p0 = 1.f / (1.f + expf(sv - bv));
        float p1 = 1.f - p0;
        int pos = atomicAdd(&g_cnt[bi], 1);
        g_list[bi * NCAP + pos] = tok;
        g_gatev[bi * NCAP + pos] = p0;
        g_tokslot[bi * NCAP + pos] = tok * 2;
        pos = atomicAdd(&g_cnt[si], 1);
        g_list[si * NCAP + pos] = tok;
        g_gatev[si * NCAP + pos] = p1;
        g_tokslot[si * NCAP + pos] = tok * 2 + 1;
    }
}

__global__ void zero_k() {
    if (threadIdx.x < NE) g_cnt[threadIdx.x] = 0;
}

__global__ void scan_k() {
    if (threadIdx.x == 0) {
        int s = 0;
        for (int e = 0; e < NE; e++) { g_off[e] = s; s += g_cnt[e]; }
    }
}

// ---------------------------------------------------------------------------
// Combine + double LN
// ---------------------------------------------------------------------------
__global__ void __launch_bounds__(256) combine_k(const float* __restrict__ gm,
                                                 const float* __restrict__ bm,
                                                 const float* __restrict__ go,
                                                 const float* __restrict__ bo) {
    int row = blockIdx.x, t = threadIdx.x;
    float4 v  = reinterpret_cast<const float4*>(g_hidden + (size_t)row * DIM)[t];
    float4 c0 = reinterpret_cast<const float4*>(g_contrib + (size_t)(2 * row) * DIM)[t];
    float4 c1 = reinterpret_cast<const float4*>(g_contrib + (size_t)(2 * row + 1) * DIM)[t];
    v.x += c0.x + c1.x; v.y += c0.y + c1.y; v.z += c0.z + c1.z; v.w += c0.w + c1.w;
    float s = v.x + v.y + v.z + v.w;
    float q = v.x * v.x + v.y * v.y + v.z * v.z + v.w * v.w;
    float mu, rs;
    row_stats1024(s, q, mu, rs);
    float4 g1 = reinterpret_cast<const float4*>(gm)[t];
    float4 b1 = reinterpret_cast<const float4*>(bm)[t];
    float4 y;
    y.x = (v.x - mu) * rs * g1.x + b1.x;
    y.y = (v.y - mu) * rs * g1.y + b1.y;
    y.z = (v.z - mu) * rs * g1.z + b1.z;
    y.w = (v.w - mu) * rs * g1.w + b1.w;
    s = y.x + y.y + y.z + y.w;
    q = y.x * y.x + y.y * y.y + y.z * y.z + y.w * y.w;
    float mu2, rs2;
    row_stats1024(s, q, mu2, rs2);
    float4 g2 = reinterpret_cast<const float4*>(go)[t];
    float4 b2 = reinterpret_cast<const float4*>(bo)[t];
    float4 o;
    o.x = (y.x - mu2) * rs2 * g2.x + b2.x;
    o.y = (y.y - mu2) * rs2 * g2.y + b2.y;
    o.z = (y.z - mu2) * rs2 * g2.z + b2.z;
    o.w = (y.w - mu2) * rs2 * g2.w + b2.w;
    reinterpret_cast<float4*>(g_final + (size_t)row * DIM)[t] = o;
}

// ---------------------------------------------------------------------------
// Classifier
// ---------------------------------------------------------------------------
__global__ void __launch_bounds__(256) cls_k(const float* __restrict__ Wc,
                                             const float* __restrict__ bc,
                                             float* __restrict__ out) {
    int tok  = blockIdx.x * 8 + (threadIdx.x >> 5);
    int lane = threadIdx.x & 31;
    const float4* h4 = reinterpret_cast<const float4*>(g_final + (size_t)tok * DIM);
    float a[8];
    #pragma unroll
    for (int ci = 0; ci < 8; ci++) a[ci] = 0.f;
    for (int t = lane; t < DIM / 4; t += 32) {
        float4 h = h4[t];
        const float* wr = Wc + (size_t)t * 4 * NC;
        #pragma unroll
        for (int u = 0; u < 4; u++) {
            float hv = (u == 0) ? h.x : (u == 1) ? h.y : (u == 2) ? h.z : h.w;
            float4 w0 = reinterpret_cast<const float4*>(wr + u * NC)[0];
            float4 w1 = reinterpret_cast<const float4*>(wr + u * NC)[1];
            a[0] += hv * w0.x; a[1] += hv * w0.y; a[2] += hv * w0.z; a[3] += hv * w0.w;
            a[4] += hv * w1.x; a[5] += hv * w1.y; a[6] += hv * w1.z; a[7] += hv * w1.w;
        }
    }
    #pragma unroll
    for (int ci = 0; ci < 8; ci++)
        #pragma unroll
        for (int o = 16; o; o >>= 1) a[ci] += __shfl_xor_sync(0xffffffffu, a[ci], o);
    if (lane == 0) {
        #pragma unroll
        for (int ci = 0; ci < 8; ci++)
            out[(size_t)tok * NC + ci] = a[ci] + bc[ci];
    }
}

// ---------------------------------------------------------------------------
// Entry point
// ---------------------------------------------------------------------------
extern "C" void kernel_launch(void* const* d_in, const int* in_sizes, int n_in,
                              void* d_out, int out_size) {
    (void)in_sizes; (void)n_in; (void)out_size;
    const float* x    = (const float*)d_in[0];
    const float* Wp   = (const float*)d_in[1];
    const float* bp   = (const float*)d_in[2];
    const float* gin  = (const float*)d_in[3];
    const float* bin  = (const float*)d_in[4];
    const float* Wg   = (const float*)d_in[5];
    const float* W1   = (const float*)d_in[6];
    const float* b1   = (const float*)d_in[7];
    const float* W2   = (const float*)d_in[8];
    const float* b2   = (const float*)d_in[9];
    const float* gmoe = (const float*)d_in[10];
    const float* bmoe = (const float*)d_in[11];
    const float* gout = (const float*)d_in[12];
    const float* bout = (const float*)d_in[13];
    const float* Wc   = (const float*)d_in[14];
    const float* bc   = (const float*)d_in[15];
    float* out = (float*)d_out;

    cudaFuncSetAttribute((const void*)gemm_tpl<0>,
                         cudaFuncAttributeMaxDynamicSharedMemorySize, SMEM_BYTES);
    cudaFuncSetAttribute((const void*)gemm_tpl<1>,
                         cudaFuncAttributeMaxDynamicSharedMemorySize, SMEM_BYTES);
    cudaFuncSetAttribute((const void*)gemm_tpl<2>,
                         cudaFuncAttributeMaxDynamicSharedMemorySize, SMEM_BYTES);

    gemm_tpl<0><<<dim3(DIM / BN, NTOK / BM, 1), 256, SMEM_BYTES>>>(x, Wp, bp, DIM, DIM, DIM);
    ln1_k<<<NTOK, 256>>>(gin, bin);
    zero_k<<<1, 32>>>();
    router_k<<<NTOK / 8, 256>>>(Wg);
    scan_k<<<1, 32>>>();
    gemm_tpl<1><<<dim3(HID / BN, NTOK / BM, NE), 256, SMEM_BYTES>>>(nullptr, W1, b1, DIM, HID, DIM);
    gemm_tpl<2><<<dim3(DIM / BN, NTOK / BM, NE), 256, SMEM_BYTES>>>(nullptr, W2, b2, HID, DIM, HID);
    combine_k<<<NTOK, 256>>>(gmoe, bmoe, gout, bout);
    cls_k<<<NTOK / 8, 256>>>(Wc, bc, out);
}